// round 4
// baseline (speedup 1.0000x reference)
#include <cuda_runtime.h>

typedef unsigned long long u64;

static constexpr int Bb = 16;
static constexpr int CE = 1024;
static constexpr int Tt = 2048;
static constexpr int CC = 64;
static constexpr int Kk = 4096;

static constexpr long long O_CODES = 0;
static constexpr long long O_QUANT = 32768;
static constexpr long long N_QUANT = (long long)Bb * CE * Tt;    // 33554432
static constexpr long long O_CBL   = O_QUANT + N_QUANT;           // 33587200
static constexpr long long O_CML   = O_CBL + 1;
static constexpr long long O_XPROJ = O_CML + 1;                   // 33587202 (even -> 8B aligned)
static constexpr long long N_XP    = (long long)Bb * CC * Tt;     // 2097152
static constexpr long long O_QPROJ = O_XPROJ + N_XP;              // 35684354 (even)

// scratch (static device globals; no runtime allocation)
__device__ __align__(16) float  g_Win[CC * CE];
__device__ __align__(16) float  g_Wout[CE * CC];
__device__ __align__(16) float  g_cbT[CC * Kk];    // normalized codebook, transposed [o][k]
__device__ __align__(16) float  g_cbn2[Kk];
__device__ double g_lpart[512];

__device__ __forceinline__ u64 pk2(float lo, float hi) {
    u64 r; asm("mov.b64 %0, {%1, %2};" : "=l"(r) : "f"(lo), "f"(hi)); return r;
}
__device__ __forceinline__ float2 upk2(u64 v) {
    float2 r; asm("mov.b64 {%0, %1}, %2;" : "=f"(r.x), "=f"(r.y) : "l"(v)); return r;
}
__device__ __forceinline__ void fma2(u64 &d, u64 a, u64 b) {
    asm("fma.rn.f32x2 %0, %1, %2, %0;" : "+l"(d) : "l"(a), "l"(b));
}

// ---------------- prep: weight-norm W_in (rows of 1024) ----------------
__global__ __launch_bounds__(256) void k_prep_win(const float* __restrict__ v_in,
                                                  const float* __restrict__ g_in)
{
    __shared__ float sb[256];
    __shared__ float snorm;
    int o = blockIdx.x, tid = threadIdx.x;
    float s = 0.f;
#pragma unroll
    for (int j = 0; j < 4; j++) { float v = v_in[o * CE + tid + j * 256]; s += v * v; }
    sb[tid] = s; __syncthreads();
    for (int off = 128; off > 0; off >>= 1) { if (tid < off) sb[tid] += sb[tid + off]; __syncthreads(); }
    if (tid == 0) snorm = __fsqrt_rn(sb[0]);
    __syncthreads();
    float n = snorm, g = g_in[o];
#pragma unroll
    for (int j = 0; j < 4; j++) {
        int i = tid + j * 256;
        g_Win[o * CE + i] = __fdiv_rn(g * v_in[o * CE + i], n);
    }
}

// ---------------- prep: weight-norm W_out (rows of 64), warp/row ----------------
__global__ __launch_bounds__(256) void k_prep_wout(const float* __restrict__ v_out,
                                                   const float* __restrict__ g_out)
{
    int gw = (blockIdx.x * 256 + threadIdx.x) >> 5;
    int l = threadIdx.x & 31;
    float a = v_out[gw * CC + l], b = v_out[gw * CC + l + 32];
    float s = a * a + b * b;
#pragma unroll
    for (int off = 16; off; off >>= 1) s += __shfl_xor_sync(0xffffffffu, s, off);
    float n = __fsqrt_rn(s), g = g_out[gw];
    g_Wout[gw * CC + l]      = __fdiv_rn(g * a, n);
    g_Wout[gw * CC + l + 32] = __fdiv_rn(g * b, n);
}

// ---------------- prep: normalize codebook -> transposed + ||.||^2 ----------------
__global__ __launch_bounds__(256) void k_prep_cb(const float* __restrict__ cb)
{
    int k = (blockIdx.x * 256 + threadIdx.x) >> 5;
    int l = threadIdx.x & 31;
    float a = cb[k * CC + l], b = cb[k * CC + l + 32];
    float s = a * a + b * b;
#pragma unroll
    for (int off = 16; off; off >>= 1) s += __shfl_xor_sync(0xffffffffu, s, off);
    float n = fmaxf(__fsqrt_rn(s), 1e-12f);
    float ca = __fdiv_rn(a, n), cbv = __fdiv_rn(b, n);
    g_cbT[l * Kk + k]        = ca;
    g_cbT[(l + 32) * Kk + k] = cbv;
    float s2 = ca * ca + cbv * cbv;
#pragma unroll
    for (int off = 16; off; off >>= 1) s2 += __shfl_xor_sync(0xffffffffu, s2, off);
    if (l == 0) g_cbn2[k] = s2;
}

// ---------------- generic: Out[64 x 2048] = W[64 x K] @ X[K x 2048] ----------------
// block = 64 o x 128 t; thread = 4 o x 8 t (two strided float4 t-groups -> conflict-free LDS.128)
template<bool XALN16>
__global__ __launch_bounds__(256) void k_gemm64(const float* __restrict__ W, int K, long long WzS,
                                                const float* __restrict__ X, long long XyS,
                                                float* __restrict__ O, long long OyS, long long OzS)
{
    __shared__ __align__(16) float Ws[32][68];
    __shared__ __align__(16) float Xs[32][128];
    const float* Wp = W + (long long)blockIdx.z * WzS;
    const float* Xp = X + (long long)blockIdx.y * XyS;
    float* Op = O + (long long)blockIdx.y * OyS + (long long)blockIdx.z * OzS + (long long)blockIdx.x * 128;
    int tid = threadIdx.x;
    int to = tid >> 4, tt = tid & 15;
    long long t0 = (long long)blockIdx.x * 128;

    u64 acc[4][4];
#pragma unroll
    for (int i = 0; i < 4; i++)
#pragma unroll
        for (int j = 0; j < 4; j++) acc[i][j] = 0ull;

    for (int kc = 0; kc < K; kc += 32) {
#pragma unroll
        for (int it = 0; it < 2; it++) {
            int rr = tid + it * 256;                 // 512 quads: 64 o x 8 kq
            int o = rr >> 3, kq = rr & 7;
            float4 w = *(const float4*)&Wp[(long long)o * K + kc + kq * 4];
            Ws[kq * 4 + 0][o] = w.x; Ws[kq * 4 + 1][o] = w.y;
            Ws[kq * 4 + 2][o] = w.z; Ws[kq * 4 + 3][o] = w.w;
        }
#pragma unroll
        for (int it = 0; it < 4; it++) {
            int rr = tid + it * 256;                 // 1024 quads: 32 k x 32 t4
            int i = rr >> 5, t4 = rr & 31;
            long long gidx = (long long)(kc + i) * Tt + t0 + t4 * 4;
            if (XALN16) {
                *(float4*)&Xs[i][t4 * 4] = *(const float4*)&Xp[gidx];
            } else {
                const u64* p = (const u64*)&Xp[gidx];
                *(u64*)&Xs[i][t4 * 4]     = p[0];
                *(u64*)&Xs[i][t4 * 4 + 2] = p[1];
            }
        }
        __syncthreads();
#pragma unroll 8
        for (int k = 0; k < 32; k++) {
            float4 w  = *(const float4*)&Ws[k][to * 4];
            float4 xa = *(const float4*)&Xs[k][tt * 4];
            float4 xb = *(const float4*)&Xs[k][64 + tt * 4];
            u64 xa0 = pk2(xa.x, xa.y), xa1 = pk2(xa.z, xa.w);
            u64 xb0 = pk2(xb.x, xb.y), xb1 = pk2(xb.z, xb.w);
            u64 w0 = pk2(w.x, w.x), w1 = pk2(w.y, w.y), w2 = pk2(w.z, w.z), w3 = pk2(w.w, w.w);
            fma2(acc[0][0], w0, xa0); fma2(acc[0][1], w0, xa1); fma2(acc[0][2], w0, xb0); fma2(acc[0][3], w0, xb1);
            fma2(acc[1][0], w1, xa0); fma2(acc[1][1], w1, xa1); fma2(acc[1][2], w1, xb0); fma2(acc[1][3], w1, xb1);
            fma2(acc[2][0], w2, xa0); fma2(acc[2][1], w2, xa1); fma2(acc[2][2], w2, xb0); fma2(acc[2][3], w2, xb1);
            fma2(acc[3][0], w3, xa0); fma2(acc[3][1], w3, xa1); fma2(acc[3][2], w3, xb0); fma2(acc[3][3], w3, xb1);
        }
        __syncthreads();
    }
#pragma unroll
    for (int oj = 0; oj < 4; oj++) {
        long long rb = (long long)(to * 4 + oj) * Tt;
        *(u64*)&Op[rb + tt * 4]          = acc[oj][0];
        *(u64*)&Op[rb + tt * 4 + 2]      = acc[oj][1];
        *(u64*)&Op[rb + 64 + tt * 4]     = acc[oj][2];
        *(u64*)&Op[rb + 64 + tt * 4 + 2] = acc[oj][3];
    }
}

// ---------------- dist + argmin + gather + qproj + loss partials ----------------
// block = 64 t; scans all 4096 codes in chunks of 64. thread = 4 t x 4 k.
__global__ __launch_bounds__(256) void k_dist(const float* __restrict__ cb,
                                              float* __restrict__ out)
{
    __shared__ __align__(16) float Es[64][68];     // [o][t] (normalized in place)
    __shared__ __align__(16) float Cs[64][68];     // [o][k-chunk]
    __shared__ __align__(16) float den[64];
    __shared__ float cbn2s[64];
    __shared__ float redv[64 * 16];
    __shared__ int   redi[64 * 16];
    __shared__ int   scode[64];

    int b = blockIdx.y, tid = threadIdx.x;
    long long t0 = (long long)blockIdx.x * 64;
    int tx = tid & 15, ty = tid >> 4;
    const long long xbase = O_XPROJ + (long long)b * (CC * Tt) + t0;

    // load x_proj tile (8B-aligned region)
#pragma unroll
    for (int it = 0; it < 4; it++) {
        int rr = tid + it * 256;
        int o = rr >> 4, t4 = rr & 15;
        const u64* p = (const u64*)&out[xbase + (long long)o * Tt + t4 * 4];
        *(u64*)&Es[o][t4 * 4]     = p[0];
        *(u64*)&Es[o][t4 * 4 + 2] = p[1];
    }
    __syncthreads();
    if (tid < 64) {
        float s = 0.f;
#pragma unroll 8
        for (int o = 0; o < 64; o++) { float v = Es[o][tid]; s += v * v; }
        den[tid] = fmaxf(__fsqrt_rn(s), 1e-12f);
    }
    __syncthreads();
#pragma unroll
    for (int it = 0; it < 4; it++) {
        int rr = tid + it * 256;
        int o = rr >> 4, t4 = rr & 15;
        float4 v = *(float4*)&Es[o][t4 * 4];
        float4 d = *(const float4*)&den[t4 * 4];
        v.x = __fdiv_rn(v.x, d.x); v.y = __fdiv_rn(v.y, d.y);
        v.z = __fdiv_rn(v.z, d.z); v.w = __fdiv_rn(v.w, d.w);
        *(float4*)&Es[o][t4 * 4] = v;
    }

    float bval[4]; int bidx[4];
#pragma unroll
    for (int i = 0; i < 4; i++) { bval[i] = 3.4028235e38f; bidx[i] = 0; }

    for (int kc = 0; kc < 64; kc++) {
        __syncthreads();
#pragma unroll
        for (int it = 0; it < 4; it++) {
            int rr = tid + it * 256;
            int o = rr >> 4, k4 = rr & 15;
            *(float4*)&Cs[o][k4 * 4] = *(const float4*)&g_cbT[o * Kk + kc * 64 + k4 * 4];
        }
        if (tid < 64) cbn2s[tid] = g_cbn2[kc * 64 + tid];
        __syncthreads();

        u64 acc[4][2];
#pragma unroll
        for (int i = 0; i < 4; i++) { acc[i][0] = 0ull; acc[i][1] = 0ull; }
#pragma unroll 8
        for (int o = 0; o < 64; o++) {
            float4 e = *(const float4*)&Es[o][ty * 4];
            float4 c = *(const float4*)&Cs[o][tx * 4];
            u64 c0 = pk2(c.x, c.y), c1 = pk2(c.z, c.w);
            u64 e0 = pk2(e.x, e.x), e1 = pk2(e.y, e.y), e2 = pk2(e.z, e.z), e3 = pk2(e.w, e.w);
            fma2(acc[0][0], e0, c0); fma2(acc[0][1], e0, c1);
            fma2(acc[1][0], e1, c0); fma2(acc[1][1], e1, c1);
            fma2(acc[2][0], e2, c0); fma2(acc[2][1], e2, c1);
            fma2(acc[3][0], e3, c0); fma2(acc[3][1], e3, c1);
        }
        // k ascending within thread; strict < keeps first min (matches jnp.argmin)
#pragma unroll
        for (int tl = 0; tl < 4; tl++) {
#pragma unroll
            for (int p = 0; p < 2; p++) {
                float2 d = upk2(acc[tl][p]);
                int kl = tx * 4 + p * 2;
                float s0 = cbn2s[kl]     - 2.f * d.x;
                float s1 = cbn2s[kl + 1] - 2.f * d.y;
                int kg = kc * 64 + kl;
                if (s0 < bval[tl]) { bval[tl] = s0; bidx[tl] = kg; }
                if (s1 < bval[tl]) { bval[tl] = s1; bidx[tl] = kg + 1; }
            }
        }
    }
#pragma unroll
    for (int tl = 0; tl < 4; tl++) {
        redv[(ty * 4 + tl) * 16 + tx] = bval[tl];
        redi[(ty * 4 + tl) * 16 + tx] = bidx[tl];
    }
    __syncthreads();
    if (tid < 64) {
        float bv = 3.4028235e38f; int bi = 0x7fffffff;
#pragma unroll
        for (int j = 0; j < 16; j++) {
            float v = redv[tid * 16 + j]; int i = redi[tid * 16 + j];
            if (v < bv || (v == bv && i < bi)) { bv = v; bi = i; }
        }
        scode[tid] = bi;
        out[O_CODES + (long long)b * Tt + t0 + tid] = (float)bi;
    }
    __syncthreads();

    // gather q, write quantized_proj = xp + (q - xp), accumulate loss
    {
        int t = tid & 63, og = tid >> 6;
        int code = scode[t];
        const float* cbrow = cb + (long long)code * CC + og * 16;
        long long xb2 = O_XPROJ + (long long)b * (CC * Tt) + t0 + t;
        long long qb2 = O_QPROJ + (long long)b * (CC * Tt) + t0 + t;
        float ls = 0.f;
#pragma unroll
        for (int j = 0; j < 16; j++) {
            long long ro = (long long)(og * 16 + j) * Tt;
            float xp = out[xb2 + ro];
            float q  = cbrow[j];
            float d  = q - xp;
            out[qb2 + ro] = xp + d;
            ls += d * d;
        }
        float* lred = redv;                         // reuse smem
        lred[tid] = ls; __syncthreads();
        for (int off = 128; off > 0; off >>= 1) {
            if (tid < off) lred[tid] += lred[tid + off];
            __syncthreads();
        }
        if (tid == 0) g_lpart[blockIdx.y * gridDim.x + blockIdx.x] = (double)lred[0];
    }
}

// ---------------- final loss reduction ----------------
__global__ __launch_bounds__(512) void k_loss(float* __restrict__ out)
{
    __shared__ double sb[512];
    int tid = threadIdx.x;
    sb[tid] = g_lpart[tid];
    __syncthreads();
    for (int off = 256; off > 0; off >>= 1) {
        if (tid < off) sb[tid] += sb[tid + off];
        __syncthreads();
    }
    if (tid == 0) {
        float l = (float)(sb[0] / (double)(16.0 * 64.0 * 2048.0));
        out[O_CBL] = l;
        out[O_CML] = l;
    }
}

extern "C" void kernel_launch(void* const* d_in, const int* in_sizes, int n_in,
                              void* d_out, int out_size) {
    (void)in_sizes; (void)n_in; (void)out_size;
    const float* x    = (const float*)d_in[0];
    const float* v_in = (const float*)d_in[1];
    const float* g_in = (const float*)d_in[2];
    const float* v_out= (const float*)d_in[3];
    const float* g_out= (const float*)d_in[4];
    const float* cb   = (const float*)d_in[5];
    float* out = (float*)d_out;

    k_prep_win<<<64, 256>>>(v_in, g_in);
    k_prep_wout<<<128, 256>>>(v_out, g_out);
    k_prep_cb<<<512, 256>>>(cb);

    float* winp; cudaGetSymbolAddress((void**)&winp, g_Win);
    float* woutp; cudaGetSymbolAddress((void**)&woutp, g_Wout);

    // x_proj = W_in @ x : per-b 64x2048, K=1024
    k_gemm64<true><<<dim3(16, 16, 1), 256>>>(winp, CE, 0ll,
                                             x, (long long)CE * Tt,
                                             out + O_XPROJ, (long long)CC * Tt, 0ll);

    // codes / qproj / loss partials
    k_dist<<<dim3(32, 16), 256>>>(cb, out);
    k_loss<<<1, 512>>>(out);

    // quantized = W_out @ quantized_proj : per-(b, o-block) 64x2048, K=64
    k_gemm64<false><<<dim3(16, 16, 16), 256>>>(woutp, CC, (long long)64 * CC,
                                               out + O_QPROJ, (long long)CC * Tt,
                                               out + O_QUANT, (long long)CE * Tt, (long long)64 * Tt);
}